// round 16
// baseline (speedup 1.0000x reference)
#include <cuda_runtime.h>
#include <cuda_bf16.h>
#include <cstdint>
#include <cstddef>

// ---------------------------------------------------------------------------
// SpanElectraGeneratorPredictionHead — split-bf16 HMMA, pipelined
// RULE: never pass __device__ globals as kernel args from host (ATS shadow).
// R14: vocab GEMM 256x256 tiles / 512 thr to halve LTS traffic.
// ---------------------------------------------------------------------------

#define DIM    768
#define SEQ    512
#define NPAIR  32
#define SPANS  256
#define PE     200
#define SPAN_L 20
#define ROWS   5120
#define EMB    128
#define VOCAB  30522
#define KSPLIT 24
#define K1LEN  64

#define VN_PAD 30720
#define KPV    384              // vocab K'
#define KP2    2304             // 3*768 K' for dim-GEMMs

#define HMMA_SMEM  65536        // 128x128 kernels: 2 x (16KB A + 16KB B)
#define VOC_SMEM  131072        // 256x256 kernel:  2 x (32KB A + 32KB B)

// scratch
__device__ float g_Ag[SPANS * 2 * DIM];
__device__ float g_P[SPAN_L * DIM];
__device__ float g_Upart[KSPLIT * SPANS * DIM];
__device__ float g_U[SPANS * DIM];
__device__ float g_pre2[ROWS * DIM];
__device__ float g_h3p[3 * ROWS * EMB];
__device__ __nv_bfloat16 g_h1s[ROWS * KP2];
__device__ __nv_bfloat16 g_h2s[ROWS * KP2];
__device__ __nv_bfloat16 g_W2s[DIM * KP2];
__device__ __nv_bfloat16 g_Wps[EMB * KP2];
__device__ __nv_bfloat16 g_A2[ROWS * KPV];
__device__ __nv_bfloat16 g_B2[VN_PAD * KPV];       // pad rows stay 0

// ---------------- packed f32x2 helpers ----------------
__device__ __forceinline__ unsigned long long pack2(float x, float y) {
    unsigned long long r;
    asm("mov.b64 %0, {%1, %2};" : "=l"(r)
        : "r"(__float_as_uint(x)), "r"(__float_as_uint(y)));
    return r;
}
__device__ __forceinline__ void unpack2(unsigned long long v, float& x, float& y) {
    unsigned a, b;
    asm("mov.b64 {%0, %1}, %2;" : "=r"(a), "=r"(b) : "l"(v));
    x = __uint_as_float(a);
    y = __uint_as_float(b);
}
__device__ __forceinline__ void fma2(unsigned long long& d,
                                     unsigned long long a, unsigned long long b) {
    asm("fma.rn.f32x2 %0, %1, %2, %0;" : "+l"(d) : "l"(a), "l"(b));
}

// ---------------- mma / ldmatrix / cp.async helpers ----------------
__device__ __forceinline__ uint32_t smem_u32(const void* p) {
    uint32_t a;
    asm("{ .reg .u64 t; cvta.to.shared.u64 t, %1; cvt.u32.u64 %0, t; }"
        : "=r"(a) : "l"(p));
    return a;
}
__device__ __forceinline__ void ldsm_x4(uint32_t& r0, uint32_t& r1,
                                        uint32_t& r2, uint32_t& r3, uint32_t addr) {
    asm volatile("ldmatrix.sync.aligned.m8n8.x4.shared.b16 {%0,%1,%2,%3}, [%4];"
                 : "=r"(r0), "=r"(r1), "=r"(r2), "=r"(r3) : "r"(addr));
}
__device__ __forceinline__ void mma16816(float* d, const uint32_t* a, const uint32_t* b) {
    asm volatile(
        "mma.sync.aligned.m16n8k16.row.col.f32.bf16.bf16.f32 "
        "{%0,%1,%2,%3}, {%4,%5,%6,%7}, {%8,%9}, {%0,%1,%2,%3};"
        : "+f"(d[0]), "+f"(d[1]), "+f"(d[2]), "+f"(d[3])
        : "r"(a[0]), "r"(a[1]), "r"(a[2]), "r"(a[3]), "r"(b[0]), "r"(b[1]));
}
__device__ __forceinline__ void cpasync16(uint32_t d, const void* g) {
    asm volatile("cp.async.cg.shared.global [%0], [%1], 16;" :: "r"(d), "l"(g) : "memory");
}

// ---------------------------------------------------------------------------
__global__ void __launch_bounds__(256) gather_kernel(const float* __restrict__ H,
                                                     const int* __restrict__ pairs) {
    int s = blockIdx.x;
    int b = s / NPAIR;
    int i0 = pairs[s * 2 + 0];
    int i1 = pairs[s * 2 + 1];
    const float* h0 = H + ((size_t)b * SEQ + i0) * DIM;
    const float* h1 = H + ((size_t)b * SEQ + i1) * DIM;
    float* dst = g_Ag + (size_t)s * (2 * DIM);
    for (int i = threadIdx.x; i < DIM; i += 256) {
        dst[i]       = h0[i];
        dst[DIM + i] = h1[i];
    }
}

__global__ void __launch_bounds__(DIM) posw_kernel(const float* __restrict__ pos_emb,
                                                   const float* __restrict__ W1,
                                                   const float* __restrict__ b1) {
    int l = blockIdx.x;
    int n = threadIdx.x;
    __shared__ float pe[PE];
    for (int i = threadIdx.x; i < PE; i += blockDim.x) pe[i] = pos_emb[l * PE + i];
    __syncthreads();
    float acc = b1[n];
    const float* Wc = W1 + (size_t)(2 * DIM) * DIM + n;
    #pragma unroll 4
    for (int k = 0; k < PE; ++k) acc = fmaf(pe[k], Wc[(size_t)k * DIM], acc);
    g_P[l * DIM + n] = acc;
}

// ---------------------------------------------------------------------------
// FFMA2 SGEMM (span GEMM only)
// ---------------------------------------------------------------------------
template<int BM, int BN, int BK, int TM, int TN>
__device__ __forceinline__ void gemm_body(
    const float* __restrict__ A, int lda,
    const float* __restrict__ B, int ldb,
    float* __restrict__ C, int ldc, int klen)
{
    __shared__ float As[BK][BM];
    __shared__ float Bs[BK][BN];
    const int tid = threadIdx.x;
    const int tx = tid & 15;
    const int ty = tid >> 4;
    const int m0 = blockIdx.y * BM;
    const int n0 = blockIdx.x * BN;
    const int k0 = blockIdx.z * klen;

    unsigned long long acc[TM / 2][TN];
    #pragma unroll
    for (int i = 0; i < TM / 2; ++i)
        #pragma unroll
        for (int j = 0; j < TN; ++j) acc[i][j] = 0ull;

    for (int kk = 0; kk < klen; kk += BK) {
        #pragma unroll
        for (int i = 0; i < (BM * BK) / 1024; ++i) {
            int q   = tid + i * 256;
            int row = q / (BK / 4);
            int kc  = (q % (BK / 4)) * 4;
            float4 v = *(const float4*)&A[(size_t)(m0 + row) * lda + (k0 + kk + kc)];
            As[kc + 0][row] = v.x; As[kc + 1][row] = v.y;
            As[kc + 2][row] = v.z; As[kc + 3][row] = v.w;
        }
        #pragma unroll
        for (int i = 0; i < (BK * BN) / 1024; ++i) {
            int q  = tid + i * 256;
            int kr = q / (BN / 4);
            int nc = (q % (BN / 4)) * 4;
            *(float4*)&Bs[kr][nc] =
                *(const float4*)&B[(size_t)(k0 + kk + kr) * ldb + (n0 + nc)];
        }
        __syncthreads();

        #pragma unroll
        for (int k = 0; k < BK; ++k) {
            unsigned long long a2[TM / 2];
            #pragma unroll
            for (int i = 0; i < TM / 2; ++i)
                a2[i] = *(const unsigned long long*)&As[k][ty * TM + 2 * i];
            #pragma unroll
            for (int j = 0; j < TN; ++j) {
                float bv = Bs[k][tx * TN + j];
                unsigned long long b2 = pack2(bv, bv);
                #pragma unroll
                for (int i = 0; i < TM / 2; ++i) fma2(acc[i][j], a2[i], b2);
            }
        }
        __syncthreads();
    }

    #pragma unroll
    for (int j = 0; j < TN; ++j) {
        int n = n0 + tx * TN + j;
        #pragma unroll
        for (int i = 0; i < TM / 2; ++i) {
            float lo, hi;
            unpack2(acc[i][j], lo, hi);
            int m = m0 + ty * TM + 2 * i;
            C[(size_t)m * ldc + n]       = lo;
            C[(size_t)(m + 1) * ldc + n] = hi;
        }
    }
}

__global__ void __launch_bounds__(256) k_gemm_span(const float* __restrict__ W1) {
    gemm_body<64, 128, 16, 4, 8>(
        g_Ag, 2 * DIM, W1, DIM,
        g_Upart + (size_t)blockIdx.z * SPANS * DIM, DIM, K1LEN);
}

__global__ void __launch_bounds__(256) reduce_U(void) {
    int idx = blockIdx.x * 256 + threadIdx.x;
    if (idx >= SPANS * DIM) return;
    float s = 0.f;
    #pragma unroll
    for (int z = 0; z < KSPLIT; ++z) s += g_Upart[(size_t)z * SPANS * DIM + idx];
    g_U[idx] = s;
}

// ---------------------------------------------------------------------------
// weight split conversions (transposed via smem -> coalesced stores along k)
// ---------------------------------------------------------------------------
__global__ void __launch_bounds__(256) conv_W2(const float* __restrict__ W2) {
    __shared__ float t[32][33];
    const int k0 = blockIdx.y * 32;
    const int n0 = blockIdx.x * 32;
    const int tx = threadIdx.x & 31;
    const int ty = threadIdx.x >> 5;
    #pragma unroll
    for (int i = 0; i < 4; ++i) {
        int k = ty + i * 8;
        t[k][tx] = W2[(size_t)(k0 + k) * DIM + n0 + tx];
    }
    __syncthreads();
    #pragma unroll
    for (int i = 0; i < 4; ++i) {
        int nn = ty + i * 8;
        float x = t[tx][nn];
        __nv_bfloat16 hi = __float2bfloat16_rn(x);
        __nv_bfloat16 lo = __float2bfloat16_rn(x - __bfloat162float(hi));
        __nv_bfloat16* d = g_W2s + (size_t)(n0 + nn) * KP2 + (k0 + tx);
        d[0]    = hi;
        d[768]  = lo;
        d[1536] = hi;
    }
}
__global__ void __launch_bounds__(256) conv_Wp(const float* __restrict__ Wp) {
    __shared__ float t[32][33];
    const int k0 = blockIdx.y * 32;
    const int n0 = blockIdx.x * 32;
    const int tx = threadIdx.x & 31;
    const int ty = threadIdx.x >> 5;
    #pragma unroll
    for (int i = 0; i < 4; ++i) {
        int k = ty + i * 8;
        t[k][tx] = Wp[(size_t)(k0 + k) * EMB + n0 + tx];
    }
    __syncthreads();
    #pragma unroll
    for (int i = 0; i < 4; ++i) {
        int nn = ty + i * 8;
        float x = t[tx][nn];
        __nv_bfloat16 hi = __float2bfloat16_rn(x);
        __nv_bfloat16 lo = __float2bfloat16_rn(x - __bfloat162float(hi));
        __nv_bfloat16* d = g_Wps + (size_t)(n0 + nn) * KP2 + (k0 + tx);
        d[0]    = hi;
        d[768]  = lo;
        d[1536] = hi;
    }
}
__global__ void __launch_bounds__(256) conv_B(const float* __restrict__ Wdec) {
    int idx = blockIdx.x * 256 + threadIdx.x;
    if (idx >= VOCAB * EMB) return;
    int n = idx / EMB, k = idx % EMB;
    float x = Wdec[idx];
    __nv_bfloat16 hi = __float2bfloat16_rn(x);
    __nv_bfloat16 lo = __float2bfloat16_rn(x - __bfloat162float(hi));
    __nv_bfloat16* d = g_B2 + (size_t)n * KPV + k;
    d[0]   = hi;
    d[128] = lo;
    d[256] = hi;
}
__global__ void __launch_bounds__(256) conv_A(const float* __restrict__ bp) {
    int idx = blockIdx.x * 256 + threadIdx.x;
    if (idx >= ROWS * EMB) return;
    int m = idx / EMB, k = idx % EMB;
    float x = g_h3p[idx] + g_h3p[ROWS * EMB + idx] + g_h3p[2 * ROWS * EMB + idx] + bp[k];
    __nv_bfloat16 hi = __float2bfloat16_rn(x);
    __nv_bfloat16 lo = __float2bfloat16_rn(x - __bfloat162float(hi));
    __nv_bfloat16* d = g_A2 + (size_t)m * KPV + k;
    d[0]   = hi;
    d[128] = hi;
    d[256] = lo;
}

// ---------------------------------------------------------------------------
// 128x128 split-bf16 HMMA body — 2-stage cp.async pipeline (gemm2 / proj)
// ---------------------------------------------------------------------------
template<int KROW, int NKI, bool BOUNDN>
__device__ __forceinline__ void hmma_body(
    const __nv_bfloat16* __restrict__ A,
    const __nv_bfloat16* __restrict__ B,
    float* __restrict__ C, int ldc, int ncols, int kbase)
{
    extern __shared__ __align__(1024) char hsm[];
    const uint32_t sbase = smem_u32(hsm);
    const int tid  = threadIdx.x;
    const int lane = tid & 31;
    const int wid  = tid >> 5;
    const int wm   = wid & 1;
    const int wn   = wid >> 1;
    const int m0 = blockIdx.y * 128;
    const int n0 = blockIdx.x * 128;

    float acc[4][4][4];
    #pragma unroll
    for (int i = 0; i < 4; ++i)
        #pragma unroll
        for (int j = 0; j < 4; ++j)
            #pragma unroll
            for (int q = 0; q < 4; ++q) acc[i][j][q] = 0.f;

    const int lrow   = tid >> 3;
    const int lchunk = tid & 7;
    const uint32_t swz = (uint32_t)((lchunk ^ (lrow & 7)) << 4);

    const int a_rsub = (lane & 7) + ((lane >> 3) & 1) * 8;
    const int a_koff = lane >> 4;
    const int b_rsub = ((lane >> 4) & 1) * 8 + (lane & 7);
    const int b_koff = (lane >> 3) & 1;

    auto load_stage = [&](int kc) {
        const uint32_t sA = sbase + (uint32_t)(kc & 1) * 32768u;
        const uint32_t sB = sA + 16384u;
        const __nv_bfloat16* ga =
            A + (size_t)(m0 + lrow) * KROW + kbase + kc * 64 + lchunk * 8;
        const __nv_bfloat16* gb =
            B + (size_t)(n0 + lrow) * KROW + kbase + kc * 64 + lchunk * 8;
        #pragma unroll
        for (int i = 0; i < 4; ++i) {
            uint32_t off = (uint32_t)(lrow + i * 32) * 128u + swz;
            cpasync16(sA + off, ga + (size_t)i * 32 * KROW);
            cpasync16(sB + off, gb + (size_t)i * 32 * KROW);
        }
        asm volatile("cp.async.commit_group;" ::: "memory");
    };

    load_stage(0);

    for (int kc = 0; kc < NKI; ++kc) {
        if (kc + 1 < NKI) {
            load_stage(kc + 1);
            asm volatile("cp.async.wait_group 1;" ::: "memory");
        } else {
            asm volatile("cp.async.wait_group 0;" ::: "memory");
        }
        __syncthreads();

        const uint32_t sA = sbase + (uint32_t)(kc & 1) * 32768u;
        const uint32_t sB = sA + 16384u;
        #pragma unroll
        for (int ks = 0; ks < 4; ++ks) {
            uint32_t a[4][4];
            #pragma unroll
            for (int i = 0; i < 4; ++i) {
                int row = wm * 64 + i * 16 + a_rsub;
                int chunk = ks * 2 + a_koff;
                ldsm_x4(a[i][0], a[i][1], a[i][2], a[i][3],
                        sA + row * 128 + ((chunk ^ (row & 7)) << 4));
            }
            #pragma unroll
            for (int h = 0; h < 2; ++h) {
                uint32_t b[4];
                int row = wn * 32 + h * 16 + b_rsub;
                int chunk = ks * 2 + b_koff;
                ldsm_x4(b[0], b[1], b[2], b[3],
                        sB + row * 128 + ((chunk ^ (row & 7)) << 4));
                #pragma unroll
                for (int i = 0; i < 4; ++i) {
                    mma16816(acc[i][2 * h],     a[i], b);
                    mma16816(acc[i][2 * h + 1], a[i], b + 2);
                }
            }
        }
        __syncthreads();
    }

    const int tq = lane >> 2, tr = lane & 3;
    #pragma unroll
    for (int i = 0; i < 4; ++i) {
        int row = m0 + wm * 64 + i * 16 + tq;
        #pragma unroll
        for (int j = 0; j < 4; ++j) {
            int col = n0 + wn * 32 + j * 8 + tr * 2;
            if (BOUNDN && col >= ncols) continue;
            *(float2*)(C + (size_t)row * ldc + col) =
                make_float2(acc[i][j][0], acc[i][j][1]);
            *(float2*)(C + (size_t)(row + 8) * ldc + col) =
                make_float2(acc[i][j][2], acc[i][j][3]);
        }
    }
}

__global__ void __launch_bounds__(256, 2) k_hmma_gemm2(void) {
    hmma_body<KP2, 36, false>(g_h1s, g_W2s, g_pre2, DIM, DIM, 0);
}
__global__ void __launch_bounds__(256, 2) k_hmma_proj(void) {
    hmma_body<KP2, 12, false>(g_h2s, g_Wps,
                              g_h3p + (size_t)blockIdx.z * ROWS * EMB,
                              EMB, EMB, blockIdx.z * 12 * 64);
}

// ---------------------------------------------------------------------------
// Vocab GEMM: 256x256 tile, 512 threads (16 warps, 4x4 of 64x64 warp tiles),
// BK=64, 2-stage cp.async, 128KB dynamic smem. Halves LTS traffic vs 128x128.
// ---------------------------------------------------------------------------
__global__ void __launch_bounds__(512, 1) k_hmma_vocab(float* __restrict__ out) {
    extern __shared__ __align__(1024) char vsm[];
    const uint32_t sbase = smem_u32(vsm);
    const int tid  = threadIdx.x;
    const int lane = tid & 31;
    const int wid  = tid >> 5;       // 0..15
    const int wm   = wid & 3;        // 4 warps along M
    const int wn   = wid >> 2;       // 4 warps along N
    const int m0 = blockIdx.y * 256;
    const int n0 = blockIdx.x * 256;

    float acc[4][8][4];
    #pragma unroll
    for (int i = 0; i < 4; ++i)
        #pragma unroll
        for (int j = 0; j < 8; ++j)
            #pragma unroll
            for (int q = 0; q < 4; ++q) acc[i][j][q] = 0.f;

    const int lrow   = tid >> 3;     // 0..63
    const int lchunk = tid & 7;
    const uint32_t swz = (uint32_t)((lchunk ^ (lrow & 7)) << 4);

    const int a_rsub = (lane & 7) + ((lane >> 3) & 1) * 8;
    const int a_koff = lane >> 4;
    const int b_rsub = ((lane >> 4) & 1) * 8 + (lane & 7);
    const int b_koff = (lane >> 3) & 1;

    auto load_stage = [&](int kc) {
        const uint32_t sA = sbase + (uint32_t)(kc & 1) * 65536u;
        const uint32_t sB = sA + 32768u;
        const __nv_bfloat16* ga =
            g_A2 + (size_t)(m0 + lrow) * KPV + kc * 64 + lchunk * 8;
        const __nv_bfloat16* gb =
            g_B2 + (size_t)(n0 + lrow) * KPV + kc * 64 + lchunk * 8;
        #pragma unroll
        for (int i = 0; i < 4; ++i) {
            uint32_t off = (uint32_t)(lrow + i * 64) * 128u + swz;
            cpasync16(sA + off, ga + (size_t)i * 64 * KPV);
            cpasync16(sB + off, gb + (size_t)i * 64 * KPV);
        }
        asm volatile("cp.async.commit_group;" ::: "memory");
    };

    load_stage(0);

    for (int kc = 0; kc < 6; ++kc) {
        if (kc + 1 < 6) {
            load_stage(kc + 1);
            asm volatile("cp.async.wait_group 1;" ::: "memory");
        } else {
            asm volatile("cp.async.wait_group 0;" ::: "memory");
        }
        __syncthreads();

        const uint32_t sA = sbase + (uint32_t)(kc & 1) * 65536u;
        const uint32_t sB = sA + 32768u;
        #pragma unroll
        for (int ks = 0; ks < 4; ++ks) {
            uint32_t a[4][4];
            #pragma unroll
            for (int i = 0; i < 4; ++i) {
                int row = wm * 64 + i * 16 + a_rsub;
                int chunk = ks * 2 + a_koff;
                ldsm_x4(a[i][0], a[i][1], a[i][2], a[i][3],
                        sA + row * 128 + ((chunk ^ (row & 7)) << 4));
            }
            #pragma unroll
            for (int h = 0; h < 4; ++h) {
                uint32_t b[4];
                int row = wn * 64 + h * 16 + b_rsub;
                int chunk = ks * 2 + b_koff;
                ldsm_x4(b[0], b[1], b[2], b[3],
                        sB + row * 128 + ((chunk ^ (row & 7)) << 4));
                #pragma unroll
                for (int i = 0; i < 4; ++i) {
                    mma16816(acc[i][2 * h],     a[i], b);
                    mma16816(acc[i][2 * h + 1], a[i], b + 2);
                }
            }
        }
        __syncthreads();
    }

    const int tq = lane >> 2, tr = lane & 3;
    #pragma unroll
    for (int i = 0; i < 4; ++i) {
        int row = m0 + wm * 64 + i * 16 + tq;
        #pragma unroll
        for (int j = 0; j < 8; ++j) {
            int col = n0 + wn * 64 + j * 8 + tr * 2;
            if (col >= VOCAB) continue;
            *(float2*)(out + (size_t)row * VOCAB + col) =
                make_float2(acc[i][j][0], acc[i][j][1]);
            *(float2*)(out + (size_t)(row + 8) * VOCAB + col) =
                make_float2(acc[i][j][2], acc[i][j][3]);
        }
    }
}

// ---------------------------------------------------------------------------
// gelu + layernorm fusions — write split-bf16 A' = [hi|hi|lo]
// ---------------------------------------------------------------------------
__device__ __forceinline__ float gelu_exact(float x) {
    return 0.5f * x * (1.0f + erff(x * 0.70710678118654752f));
}
__device__ __forceinline__ void store_split(__nv_bfloat16* rowp, int n, float x) {
    __nv_bfloat16 hi = __float2bfloat16_rn(x);
    __nv_bfloat16 lo = __float2bfloat16_rn(x - __bfloat162float(hi));
    rowp[n]        = hi;
    rowp[768 + n]  = hi;
    rowp[1536 + n] = lo;
}

__global__ void __launch_bounds__(256) fuse_ln1(const float* __restrict__ g,
                                                const float* __restrict__ be) {
    int r = blockIdx.x;
    int s = r / SPAN_L;
    int l = r % SPAN_L;
    __shared__ float shs[8], shq[8];
    float v[3];
    float sum = 0.f, sq = 0.f;
    #pragma unroll
    for (int j = 0; j < 3; ++j) {
        int n = threadIdx.x + j * 256;
        float x = g_P[l * DIM + n] + g_U[s * DIM + n];
        float ge = gelu_exact(x);
        v[j] = ge;
        sum += ge;
        sq  += ge * ge;
    }
    #pragma unroll
    for (int o = 16; o > 0; o >>= 1) {
        sum += __shfl_xor_sync(0xffffffffu, sum, o);
        sq  += __shfl_xor_sync(0xffffffffu, sq, o);
    }
    if ((threadIdx.x & 31) == 0) { shs[threadIdx.x >> 5] = sum; shq[threadIdx.x >> 5] = sq; }
    __syncthreads();
    float ts = 0.f, tq = 0.f;
    #pragma unroll
    for (int w = 0; w < 8; ++w) { ts += shs[w]; tq += shq[w]; }
    float mean = ts * (1.0f / DIM);
    float var  = tq * (1.0f / DIM) - mean * mean;
    float rstd = rsqrtf(var + 1e-12f);
    __nv_bfloat16* rowp = g_h1s + (size_t)r * KP2;
    #pragma unroll
    for (int j = 0; j < 3; ++j) {
        int n = threadIdx.x + j * 256;
        store_split(rowp, n, (v[j] - mean) * rstd * g[n] + be[n]);
    }
}

__global__ void __launch_bounds__(256) fuse_ln2(const float* __restrict__ bias,
                                                const float* __restrict__ g,
                                                const float* __restrict__ be) {
    int r = blockIdx.x;
    __shared__ float shs[8], shq[8];
    float v[3];
    float sum = 0.f, sq = 0.f;
    #pragma unroll
    for (int j = 0; j < 3; ++j) {
        int n = threadIdx.x + j * 256;
        float x = g_pre2[(size_t)r * DIM + n] + bias[n];
        float ge = gelu_exact(x);
        v[j] = ge;
        sum += ge;
        sq  += ge * ge;
    }
    #pragma unroll
    for (int o = 16; o > 0; o >>= 1) {
        sum += __shfl_xor_sync(0xffffffffu, sum, o);
        sq  += __shfl_xor_sync(0xffffffffu, sq, o);
    }
    if ((threadIdx.x & 31) == 0) { shs[threadIdx.x >> 5] = sum; shq[threadIdx.x >> 5] = sq; }
    __syncthreads();
    float ts = 0.f, tq = 0.f;
    #pragma unroll
    for (int w = 0; w < 8; ++w) { ts += shs[w]; tq += shq[w]; }
    float mean = ts * (1.0f / DIM);
    float var  = tq * (1.0f / DIM) - mean * mean;
    float rstd = rsqrtf(var + 1e-12f);
    __nv_bfloat16* rowp = g_h2s + (size_t)r * KP2;
    #pragma unroll
    for (int j = 0; j < 3; ++j) {
        int n = threadIdx.x + j * 256;
        store_split(rowp, n, (v[j] - mean) * rstd * g[n] + be[n]);
    }
}

// ---------------------------------------------------------------------------
extern "C" void kernel_launch(void* const* d_in, const int* in_sizes, int n_in,
                              void* d_out, int out_size) {
    const float* H       = (const float*)d_in[0];
    const int*   pairs   = (const int*)  d_in[1];
    const float* pos_emb = (const float*)d_in[2];
    const float* W1      = (const float*)d_in[3];
    const float* b1      = (const float*)d_in[4];
    const float* g1      = (const float*)d_in[5];
    const float* be1     = (const float*)d_in[6];
    const float* W2      = (const float*)d_in[7];
    const float* b2      = (const float*)d_in[8];
    const float* g2      = (const float*)d_in[9];
    const float* be2     = (const float*)d_in[10];
    const float* Wp      = (const float*)d_in[11];
    const float* bp      = (const float*)d_in[12];
    const float* Wdec    = (const float*)d_in[13];
    float* out = (float*)d_out;

    cudaFuncSetAttribute(k_hmma_gemm2,
                         cudaFuncAttributeMaxDynamicSharedMemorySize, HMMA_SMEM);
    cudaFuncSetAttribute(k_hmma_proj,
                         cudaFuncAttributeMaxDynamicSharedMemorySize, HMMA_SMEM);
    cudaFuncSetAttribute(k_hmma_vocab,
                         cudaFuncAttributeMaxDynamicSharedMemorySize, VOC_SMEM);

    gather_kernel<<<SPANS, 256>>>(H, pairs);
    posw_kernel<<<SPAN_L, DIM>>>(pos_emb, W1, b1);
    conv_B<<<(VOCAB * EMB + 255) / 256, 256>>>(Wdec);
    conv_W2<<<dim3(DIM / 32, DIM / 32), 256>>>(W2);
    conv_Wp<<<dim3(EMB / 32, DIM / 32), 256>>>(Wp);
    k_gemm_span<<<dim3(DIM / 128, SPANS / 64, KSPLIT), 256>>>(W1);
    reduce_U<<<(SPANS * DIM + 255) / 256, 256>>>();
    fuse_ln1<<<ROWS, 256>>>(g1, be1);
    k_hmma_gemm2<<<dim3(DIM / 128, ROWS / 128, 1), 256, HMMA_SMEM>>>();
    fuse_ln2<<<ROWS, 256>>>(b2, g2, be2);
    k_hmma_proj<<<dim3(1, ROWS / 128, 3), 256, HMMA_SMEM>>>();
    conv_A<<<(ROWS * EMB + 255) / 256, 256>>>(bp);
    k_hmma_vocab<<<dim3(VN_PAD / 256, ROWS / 256, 1), 512, VOC_SMEM>>>(out);
}

// round 17
// speedup vs baseline: 2.0220x; 2.0220x over previous
#include <cuda_runtime.h>
#include <cuda_bf16.h>
#include <cstdint>
#include <cstddef>

// ---------------------------------------------------------------------------
// SpanElectraGeneratorPredictionHead — split-bf16 HMMA, pipelined
// RULES learned:
//  - never pass __device__ globals as kernel args from host (ATS shadow)
//  - per-thread acc floats = BM*BN/nthreads must be <= ~64 (reg cap = 64K/thr)
// R17: vocab 128x256 / 512 thr (acc=64/thr) -> -25% LTS traffic, no spill.
// ---------------------------------------------------------------------------

#define DIM    768
#define SEQ    512
#define NPAIR  32
#define SPANS  256
#define PE     200
#define SPAN_L 20
#define ROWS   5120
#define EMB    128
#define VOCAB  30522
#define KSPLIT 24
#define K1LEN  64

#define VN_PAD 30720
#define KPV    384              // vocab K'
#define KP2    2304             // 3*768 K' for dim-GEMMs

#define HMMA_SMEM 65536         // 128x128 kernels: 2 x (16KB A + 16KB B)
#define VOC_SMEM  98304         // 128x256 kernel:  2 x (16KB A + 32KB B)

// scratch
__device__ float g_Ag[SPANS * 2 * DIM];
__device__ float g_P[SPAN_L * DIM];
__device__ float g_Upart[KSPLIT * SPANS * DIM];
__device__ float g_U[SPANS * DIM];
__device__ float g_pre2[ROWS * DIM];
__device__ float g_h3p[3 * ROWS * EMB];
__device__ __nv_bfloat16 g_h1s[ROWS * KP2];
__device__ __nv_bfloat16 g_h2s[ROWS * KP2];
__device__ __nv_bfloat16 g_W2s[DIM * KP2];
__device__ __nv_bfloat16 g_Wps[EMB * KP2];
__device__ __nv_bfloat16 g_A2[ROWS * KPV];
__device__ __nv_bfloat16 g_B2[VN_PAD * KPV];       // pad rows stay 0

// ---------------- packed f32x2 helpers ----------------
__device__ __forceinline__ unsigned long long pack2(float x, float y) {
    unsigned long long r;
    asm("mov.b64 %0, {%1, %2};" : "=l"(r)
        : "r"(__float_as_uint(x)), "r"(__float_as_uint(y)));
    return r;
}
__device__ __forceinline__ void unpack2(unsigned long long v, float& x, float& y) {
    unsigned a, b;
    asm("mov.b64 {%0, %1}, %2;" : "=r"(a), "=r"(b) : "l"(v));
    x = __uint_as_float(a);
    y = __uint_as_float(b);
}
__device__ __forceinline__ void fma2(unsigned long long& d,
                                     unsigned long long a, unsigned long long b) {
    asm("fma.rn.f32x2 %0, %1, %2, %0;" : "+l"(d) : "l"(a), "l"(b));
}

// ---------------- mma / ldmatrix / cp.async helpers ----------------
__device__ __forceinline__ uint32_t smem_u32(const void* p) {
    uint32_t a;
    asm("{ .reg .u64 t; cvta.to.shared.u64 t, %1; cvt.u32.u64 %0, t; }"
        : "=r"(a) : "l"(p));
    return a;
}
__device__ __forceinline__ void ldsm_x4(uint32_t& r0, uint32_t& r1,
                                        uint32_t& r2, uint32_t& r3, uint32_t addr) {
    asm volatile("ldmatrix.sync.aligned.m8n8.x4.shared.b16 {%0,%1,%2,%3}, [%4];"
                 : "=r"(r0), "=r"(r1), "=r"(r2), "=r"(r3) : "r"(addr));
}
__device__ __forceinline__ void mma16816(float* d, const uint32_t* a, const uint32_t* b) {
    asm volatile(
        "mma.sync.aligned.m16n8k16.row.col.f32.bf16.bf16.f32 "
        "{%0,%1,%2,%3}, {%4,%5,%6,%7}, {%8,%9}, {%0,%1,%2,%3};"
        : "+f"(d[0]), "+f"(d[1]), "+f"(d[2]), "+f"(d[3])
        : "r"(a[0]), "r"(a[1]), "r"(a[2]), "r"(a[3]), "r"(b[0]), "r"(b[1]));
}
__device__ __forceinline__ void cpasync16(uint32_t d, const void* g) {
    asm volatile("cp.async.cg.shared.global [%0], [%1], 16;" :: "r"(d), "l"(g) : "memory");
}

// ---------------------------------------------------------------------------
__global__ void __launch_bounds__(256) gather_kernel(const float* __restrict__ H,
                                                     const int* __restrict__ pairs) {
    int s = blockIdx.x;
    int b = s / NPAIR;
    int i0 = pairs[s * 2 + 0];
    int i1 = pairs[s * 2 + 1];
    const float* h0 = H + ((size_t)b * SEQ + i0) * DIM;
    const float* h1 = H + ((size_t)b * SEQ + i1) * DIM;
    float* dst = g_Ag + (size_t)s * (2 * DIM);
    for (int i = threadIdx.x; i < DIM; i += 256) {
        dst[i]       = h0[i];
        dst[DIM + i] = h1[i];
    }
}

__global__ void __launch_bounds__(DIM) posw_kernel(const float* __restrict__ pos_emb,
                                                   const float* __restrict__ W1,
                                                   const float* __restrict__ b1) {
    int l = blockIdx.x;
    int n = threadIdx.x;
    __shared__ float pe[PE];
    for (int i = threadIdx.x; i < PE; i += blockDim.x) pe[i] = pos_emb[l * PE + i];
    __syncthreads();
    float acc = b1[n];
    const float* Wc = W1 + (size_t)(2 * DIM) * DIM + n;
    #pragma unroll 4
    for (int k = 0; k < PE; ++k) acc = fmaf(pe[k], Wc[(size_t)k * DIM], acc);
    g_P[l * DIM + n] = acc;
}

// ---------------------------------------------------------------------------
// FFMA2 SGEMM (span GEMM only)
// ---------------------------------------------------------------------------
template<int BM, int BN, int BK, int TM, int TN>
__device__ __forceinline__ void gemm_body(
    const float* __restrict__ A, int lda,
    const float* __restrict__ B, int ldb,
    float* __restrict__ C, int ldc, int klen)
{
    __shared__ float As[BK][BM];
    __shared__ float Bs[BK][BN];
    const int tid = threadIdx.x;
    const int tx = tid & 15;
    const int ty = tid >> 4;
    const int m0 = blockIdx.y * BM;
    const int n0 = blockIdx.x * BN;
    const int k0 = blockIdx.z * klen;

    unsigned long long acc[TM / 2][TN];
    #pragma unroll
    for (int i = 0; i < TM / 2; ++i)
        #pragma unroll
        for (int j = 0; j < TN; ++j) acc[i][j] = 0ull;

    for (int kk = 0; kk < klen; kk += BK) {
        #pragma unroll
        for (int i = 0; i < (BM * BK) / 1024; ++i) {
            int q   = tid + i * 256;
            int row = q / (BK / 4);
            int kc  = (q % (BK / 4)) * 4;
            float4 v = *(const float4*)&A[(size_t)(m0 + row) * lda + (k0 + kk + kc)];
            As[kc + 0][row] = v.x; As[kc + 1][row] = v.y;
            As[kc + 2][row] = v.z; As[kc + 3][row] = v.w;
        }
        #pragma unroll
        for (int i = 0; i < (BK * BN) / 1024; ++i) {
            int q  = tid + i * 256;
            int kr = q / (BN / 4);
            int nc = (q % (BN / 4)) * 4;
            *(float4*)&Bs[kr][nc] =
                *(const float4*)&B[(size_t)(k0 + kk + kr) * ldb + (n0 + nc)];
        }
        __syncthreads();

        #pragma unroll
        for (int k = 0; k < BK; ++k) {
            unsigned long long a2[TM / 2];
            #pragma unroll
            for (int i = 0; i < TM / 2; ++i)
                a2[i] = *(const unsigned long long*)&As[k][ty * TM + 2 * i];
            #pragma unroll
            for (int j = 0; j < TN; ++j) {
                float bv = Bs[k][tx * TN + j];
                unsigned long long b2 = pack2(bv, bv);
                #pragma unroll
                for (int i = 0; i < TM / 2; ++i) fma2(acc[i][j], a2[i], b2);
            }
        }
        __syncthreads();
    }

    #pragma unroll
    for (int j = 0; j < TN; ++j) {
        int n = n0 + tx * TN + j;
        #pragma unroll
        for (int i = 0; i < TM / 2; ++i) {
            float lo, hi;
            unpack2(acc[i][j], lo, hi);
            int m = m0 + ty * TM + 2 * i;
            C[(size_t)m * ldc + n]       = lo;
            C[(size_t)(m + 1) * ldc + n] = hi;
        }
    }
}

__global__ void __launch_bounds__(256) k_gemm_span(const float* __restrict__ W1) {
    gemm_body<64, 128, 16, 4, 8>(
        g_Ag, 2 * DIM, W1, DIM,
        g_Upart + (size_t)blockIdx.z * SPANS * DIM, DIM, K1LEN);
}

__global__ void __launch_bounds__(256) reduce_U(void) {
    int idx = blockIdx.x * 256 + threadIdx.x;
    if (idx >= SPANS * DIM) return;
    float s = 0.f;
    #pragma unroll
    for (int z = 0; z < KSPLIT; ++z) s += g_Upart[(size_t)z * SPANS * DIM + idx];
    g_U[idx] = s;
}

// ---------------------------------------------------------------------------
// weight split conversions (transposed via smem -> coalesced stores along k)
// ---------------------------------------------------------------------------
__global__ void __launch_bounds__(256) conv_W2(const float* __restrict__ W2) {
    __shared__ float t[32][33];
    const int k0 = blockIdx.y * 32;
    const int n0 = blockIdx.x * 32;
    const int tx = threadIdx.x & 31;
    const int ty = threadIdx.x >> 5;
    #pragma unroll
    for (int i = 0; i < 4; ++i) {
        int k = ty + i * 8;
        t[k][tx] = W2[(size_t)(k0 + k) * DIM + n0 + tx];
    }
    __syncthreads();
    #pragma unroll
    for (int i = 0; i < 4; ++i) {
        int nn = ty + i * 8;
        float x = t[tx][nn];
        __nv_bfloat16 hi = __float2bfloat16_rn(x);
        __nv_bfloat16 lo = __float2bfloat16_rn(x - __bfloat162float(hi));
        __nv_bfloat16* d = g_W2s + (size_t)(n0 + nn) * KP2 + (k0 + tx);
        d[0]    = hi;
        d[768]  = lo;
        d[1536] = hi;
    }
}
__global__ void __launch_bounds__(256) conv_Wp(const float* __restrict__ Wp) {
    __shared__ float t[32][33];
    const int k0 = blockIdx.y * 32;
    const int n0 = blockIdx.x * 32;
    const int tx = threadIdx.x & 31;
    const int ty = threadIdx.x >> 5;
    #pragma unroll
    for (int i = 0; i < 4; ++i) {
        int k = ty + i * 8;
        t[k][tx] = Wp[(size_t)(k0 + k) * EMB + n0 + tx];
    }
    __syncthreads();
    #pragma unroll
    for (int i = 0; i < 4; ++i) {
        int nn = ty + i * 8;
        float x = t[tx][nn];
        __nv_bfloat16 hi = __float2bfloat16_rn(x);
        __nv_bfloat16 lo = __float2bfloat16_rn(x - __bfloat162float(hi));
        __nv_bfloat16* d = g_Wps + (size_t)(n0 + nn) * KP2 + (k0 + tx);
        d[0]    = hi;
        d[768]  = lo;
        d[1536] = hi;
    }
}
__global__ void __launch_bounds__(256) conv_B(const float* __restrict__ Wdec) {
    int idx = blockIdx.x * 256 + threadIdx.x;
    if (idx >= VOCAB * EMB) return;
    int n = idx / EMB, k = idx % EMB;
    float x = Wdec[idx];
    __nv_bfloat16 hi = __float2bfloat16_rn(x);
    __nv_bfloat16 lo = __float2bfloat16_rn(x - __bfloat162float(hi));
    __nv_bfloat16* d = g_B2 + (size_t)n * KPV + k;
    d[0]   = hi;
    d[128] = lo;
    d[256] = hi;
}
__global__ void __launch_bounds__(256) conv_A(const float* __restrict__ bp) {
    int idx = blockIdx.x * 256 + threadIdx.x;
    if (idx >= ROWS * EMB) return;
    int m = idx / EMB, k = idx % EMB;
    float x = g_h3p[idx] + g_h3p[ROWS * EMB + idx] + g_h3p[2 * ROWS * EMB + idx] + bp[k];
    __nv_bfloat16 hi = __float2bfloat16_rn(x);
    __nv_bfloat16 lo = __float2bfloat16_rn(x - __bfloat162float(hi));
    __nv_bfloat16* d = g_A2 + (size_t)m * KPV + k;
    d[0]   = hi;
    d[128] = hi;
    d[256] = lo;
}

// ---------------------------------------------------------------------------
// 128x128 split-bf16 HMMA body — 2-stage cp.async pipeline (gemm2 / proj)
// ---------------------------------------------------------------------------
template<int KROW, int NKI, bool BOUNDN>
__device__ __forceinline__ void hmma_body(
    const __nv_bfloat16* __restrict__ A,
    const __nv_bfloat16* __restrict__ B,
    float* __restrict__ C, int ldc, int ncols, int kbase)
{
    extern __shared__ __align__(1024) char hsm[];
    const uint32_t sbase = smem_u32(hsm);
    const int tid  = threadIdx.x;
    const int lane = tid & 31;
    const int wid  = tid >> 5;
    const int wm   = wid & 1;
    const int wn   = wid >> 1;
    const int m0 = blockIdx.y * 128;
    const int n0 = blockIdx.x * 128;

    float acc[4][4][4];
    #pragma unroll
    for (int i = 0; i < 4; ++i)
        #pragma unroll
        for (int j = 0; j < 4; ++j)
            #pragma unroll
            for (int q = 0; q < 4; ++q) acc[i][j][q] = 0.f;

    const int lrow   = tid >> 3;
    const int lchunk = tid & 7;
    const uint32_t swz = (uint32_t)((lchunk ^ (lrow & 7)) << 4);

    const int a_rsub = (lane & 7) + ((lane >> 3) & 1) * 8;
    const int a_koff = lane >> 4;
    const int b_rsub = ((lane >> 4) & 1) * 8 + (lane & 7);
    const int b_koff = (lane >> 3) & 1;

    auto load_stage = [&](int kc) {
        const uint32_t sA = sbase + (uint32_t)(kc & 1) * 32768u;
        const uint32_t sB = sA + 16384u;
        const __nv_bfloat16* ga =
            A + (size_t)(m0 + lrow) * KROW + kbase + kc * 64 + lchunk * 8;
        const __nv_bfloat16* gb =
            B + (size_t)(n0 + lrow) * KROW + kbase + kc * 64 + lchunk * 8;
        #pragma unroll
        for (int i = 0; i < 4; ++i) {
            uint32_t off = (uint32_t)(lrow + i * 32) * 128u + swz;
            cpasync16(sA + off, ga + (size_t)i * 32 * KROW);
            cpasync16(sB + off, gb + (size_t)i * 32 * KROW);
        }
        asm volatile("cp.async.commit_group;" ::: "memory");
    };

    load_stage(0);

    for (int kc = 0; kc < NKI; ++kc) {
        if (kc + 1 < NKI) {
            load_stage(kc + 1);
            asm volatile("cp.async.wait_group 1;" ::: "memory");
        } else {
            asm volatile("cp.async.wait_group 0;" ::: "memory");
        }
        __syncthreads();

        const uint32_t sA = sbase + (uint32_t)(kc & 1) * 32768u;
        const uint32_t sB = sA + 16384u;
        #pragma unroll
        for (int ks = 0; ks < 4; ++ks) {
            uint32_t a[4][4];
            #pragma unroll
            for (int i = 0; i < 4; ++i) {
                int row = wm * 64 + i * 16 + a_rsub;
                int chunk = ks * 2 + a_koff;
                ldsm_x4(a[i][0], a[i][1], a[i][2], a[i][3],
                        sA + row * 128 + ((chunk ^ (row & 7)) << 4));
            }
            #pragma unroll
            for (int h = 0; h < 2; ++h) {
                uint32_t b[4];
                int row = wn * 32 + h * 16 + b_rsub;
                int chunk = ks * 2 + b_koff;
                ldsm_x4(b[0], b[1], b[2], b[3],
                        sB + row * 128 + ((chunk ^ (row & 7)) << 4));
                #pragma unroll
                for (int i = 0; i < 4; ++i) {
                    mma16816(acc[i][2 * h],     a[i], b);
                    mma16816(acc[i][2 * h + 1], a[i], b + 2);
                }
            }
        }
        __syncthreads();
    }

    const int tq = lane >> 2, tr = lane & 3;
    #pragma unroll
    for (int i = 0; i < 4; ++i) {
        int row = m0 + wm * 64 + i * 16 + tq;
        #pragma unroll
        for (int j = 0; j < 4; ++j) {
            int col = n0 + wn * 32 + j * 8 + tr * 2;
            if (BOUNDN && col >= ncols) continue;
            *(float2*)(C + (size_t)row * ldc + col) =
                make_float2(acc[i][j][0], acc[i][j][1]);
            *(float2*)(C + (size_t)(row + 8) * ldc + col) =
                make_float2(acc[i][j][2], acc[i][j][3]);
        }
    }
}

__global__ void __launch_bounds__(256, 2) k_hmma_gemm2(void) {
    hmma_body<KP2, 36, false>(g_h1s, g_W2s, g_pre2, DIM, DIM, 0);
}
__global__ void __launch_bounds__(256, 2) k_hmma_proj(void) {
    hmma_body<KP2, 12, false>(g_h2s, g_Wps,
                              g_h3p + (size_t)blockIdx.z * ROWS * EMB,
                              EMB, EMB, blockIdx.z * 12 * 64);
}

// ---------------------------------------------------------------------------
// Vocab GEMM: 128x256 tile, 512 threads (16 warps 4x4, warp tile 32x64),
// BK=64, 2-stage cp.async, 96KB dynamic smem. acc = 64 floats/thread.
// ---------------------------------------------------------------------------
__global__ void __launch_bounds__(512, 1) k_hmma_vocab(float* __restrict__ out) {
    extern __shared__ __align__(1024) char vsm[];
    const uint32_t sbase = smem_u32(vsm);
    const int tid  = threadIdx.x;
    const int lane = tid & 31;
    const int wid  = tid >> 5;       // 0..15
    const int wm   = wid & 3;        // 4 warps along M (32 rows each)
    const int wn   = wid >> 2;       // 4 warps along N (64 cols each)
    const int m0 = blockIdx.y * 128;
    const int n0 = blockIdx.x * 256;

    float acc[2][8][4];
    #pragma unroll
    for (int i = 0; i < 2; ++i)
        #pragma unroll
        for (int j = 0; j < 8; ++j)
            #pragma unroll
            for (int q = 0; q < 4; ++q) acc[i][j][q] = 0.f;

    const int lrow   = tid >> 3;     // 0..63
    const int lchunk = tid & 7;
    const uint32_t swz = (uint32_t)((lchunk ^ (lrow & 7)) << 4);

    const int a_rsub = (lane & 7) + ((lane >> 3) & 1) * 8;
    const int a_koff = lane >> 4;
    const int b_rsub = ((lane >> 4) & 1) * 8 + (lane & 7);
    const int b_koff = (lane >> 3) & 1;

    auto load_stage = [&](int kc) {
        const uint32_t sA = sbase + (uint32_t)(kc & 1) * 49152u;
        const uint32_t sB = sA + 16384u;
        const __nv_bfloat16* ga =
            g_A2 + (size_t)(m0 + lrow) * KPV + kc * 64 + lchunk * 8;
        const __nv_bfloat16* gb =
            g_B2 + (size_t)(n0 + lrow) * KPV + kc * 64 + lchunk * 8;
        #pragma unroll
        for (int i = 0; i < 2; ++i) {
            uint32_t off = (uint32_t)(lrow + i * 64) * 128u + swz;
            cpasync16(sA + off, ga + (size_t)i * 64 * KPV);
        }
        #pragma unroll
        for (int i = 0; i < 4; ++i) {
            uint32_t off = (uint32_t)(lrow + i * 64) * 128u + swz;
            cpasync16(sB + off, gb + (size_t)i * 64 * KPV);
        }
        asm volatile("cp.async.commit_group;" ::: "memory");
    };

    load_stage(0);

    for (int kc = 0; kc < 6; ++kc) {
        if (kc + 1 < 6) {
            load_stage(kc + 1);
            asm volatile("cp.async.wait_group 1;" ::: "memory");
        } else {
            asm volatile("cp.async.wait_group 0;" ::: "memory");
        }
        __syncthreads();

        const uint32_t sA = sbase + (uint32_t)(kc & 1) * 49152u;
        const uint32_t sB = sA + 16384u;
        #pragma unroll
        for (int ks = 0; ks < 4; ++ks) {
            uint32_t a[2][4];
            #pragma unroll
            for (int i = 0; i < 2; ++i) {
                int row = wm * 32 + i * 16 + a_rsub;
                int chunk = ks * 2 + a_koff;
                ldsm_x4(a[i][0], a[i][1], a[i][2], a[i][3],
                        sA + row * 128 + ((chunk ^ (row & 7)) << 4));
            }
            #pragma unroll
            for (int h = 0; h < 4; ++h) {
                uint32_t b[4];
                int row = wn * 64 + h * 16 + b_rsub;
                int chunk = ks * 2 + b_koff;
                ldsm_x4(b[0], b[1], b[2], b[3],
                        sB + row * 128 + ((chunk ^ (row & 7)) << 4));
                #pragma unroll
                for (int i = 0; i < 2; ++i) {
                    mma16816(acc[i][2 * h],     a[i], b);
                    mma16816(acc[i][2 * h + 1], a[i], b + 2);
                }
            }
        }
        __syncthreads();
    }

    const int tq = lane >> 2, tr = lane & 3;
    #pragma unroll
    for (int i = 0; i < 2; ++i) {
        int row = m0 + wm * 32 + i * 16 + tq;
        #pragma unroll
        for (int j = 0; j < 8; ++j) {
            int col = n0 + wn * 64 + j * 8 + tr * 2;
            if (col >= VOCAB) continue;
            *(float2*)(out + (size_t)row * VOCAB + col) =
                make_float2(acc[i][j][0], acc[i][j][1]);
            *(float2*)(out + (size_t)(row + 8) * VOCAB + col) =
                make_float2(acc[i][j][2], acc[i][j][3]);
        }
    }
}

// ---------------------------------------------------------------------------
// gelu + layernorm fusions — write split-bf16 A' = [hi|hi|lo]
// ---------------------------------------------------------------------------
__device__ __forceinline__ float gelu_exact(float x) {
    return 0.5f * x * (1.0f + erff(x * 0.70710678118654752f));
}
__device__ __forceinline__ void store_split(__nv_bfloat16* rowp, int n, float x) {
    __nv_bfloat16 hi = __float2bfloat16_rn(x);
    __nv_bfloat16 lo = __float2bfloat16_rn(x - __bfloat162float(hi));
    rowp[n]        = hi;
    rowp[768 + n]  = hi;
    rowp[1536 + n] = lo;
}

__global__ void __launch_bounds__(256) fuse_ln1(const float* __restrict__ g,
                                                const float* __restrict__ be) {
    int r = blockIdx.x;
    int s = r / SPAN_L;
    int l = r % SPAN_L;
    __shared__ float shs[8], shq[8];
    float v[3];
    float sum = 0.f, sq = 0.f;
    #pragma unroll
    for (int j = 0; j < 3; ++j) {
        int n = threadIdx.x + j * 256;
        float x = g_P[l * DIM + n] + g_U[s * DIM + n];
        float ge = gelu_exact(x);
        v[j] = ge;
        sum += ge;
        sq  += ge * ge;
    }
    #pragma unroll
    for (int o = 16; o > 0; o >>= 1) {
        sum += __shfl_xor_sync(0xffffffffu, sum, o);
        sq  += __shfl_xor_sync(0xffffffffu, sq, o);
    }
    if ((threadIdx.x & 31) == 0) { shs[threadIdx.x >> 5] = sum; shq[threadIdx.x >> 5] = sq; }
    __syncthreads();
    float ts = 0.f, tq = 0.f;
    #pragma unroll
    for (int w = 0; w < 8; ++w) { ts += shs[w]; tq += shq[w]; }
    float mean = ts * (1.0f / DIM);
    float var  = tq * (1.0f / DIM) - mean * mean;
    float rstd = rsqrtf(var + 1e-12f);
    __nv_bfloat16* rowp = g_h1s + (size_t)r * KP2;
    #pragma unroll
    for (int j = 0; j < 3; ++j) {
        int n = threadIdx.x + j * 256;
        store_split(rowp, n, (v[j] - mean) * rstd * g[n] + be[n]);
    }
}

__global__ void __launch_bounds__(256) fuse_ln2(const float* __restrict__ bias,
                                                const float* __restrict__ g,
                                                const float* __restrict__ be) {
    int r = blockIdx.x;
    __shared__ float shs[8], shq[8];
    float v[3];
    float sum = 0.f, sq = 0.f;
    #pragma unroll
    for (int j = 0; j < 3; ++j) {
        int n = threadIdx.x + j * 256;
        float x = g_pre2[(size_t)r * DIM + n] + bias[n];
        float ge = gelu_exact(x);
        v[j] = ge;
        sum += ge;
        sq  += ge * ge;
    }
    #pragma unroll
    for (int o = 16; o > 0; o >>= 1) {
        sum += __shfl_xor_sync(0xffffffffu, sum, o);
        sq  += __shfl_xor_sync(0xffffffffu, sq, o);
    }
    if ((threadIdx.x & 31) == 0) { shs[threadIdx.x >> 5] = sum; shq[threadIdx.x >> 5] = sq; }
    __syncthreads();
    float ts = 0.f, tq = 0.f;
    #pragma unroll
    for (int w = 0; w < 8; ++w) { ts += shs[w]; tq += shq[w]; }
    float mean = ts * (1.0f / DIM);
    float var  = tq * (1.0f / DIM) - mean * mean;
    float rstd = rsqrtf(var + 1e-12f);
    __nv_bfloat16* rowp = g_h2s + (size_t)r * KP2;
    #pragma unroll
    for (int j = 0; j < 3; ++j) {
        int n = threadIdx.x + j * 256;
        store_split(rowp, n, (v[j] - mean) * rstd * g[n] + be[n]);
    }
}

// ---------------------------------------------------------------------------
extern "C" void kernel_launch(void* const* d_in, const int* in_sizes, int n_in,
                              void* d_out, int out_size) {
    const float* H       = (const float*)d_in[0];
    const int*   pairs   = (const int*)  d_in[1];
    const float* pos_emb = (const float*)d_in[2];
    const float* W1      = (const float*)d_in[3];
    const float* b1      = (const float*)d_in[4];
    const float* g1      = (const float*)d_in[5];
    const float* be1     = (const float*)d_in[6];
    const float* W2      = (const float*)d_in[7];
    const float* b2      = (const float*)d_in[8];
    const float* g2      = (const float*)d_in[9];
    const float* be2     = (const float*)d_in[10];
    const float* Wp      = (const float*)d_in[11];
    const float* bp      = (const float*)d_in[12];
    const float* Wdec    = (const float*)d_in[13];
    float* out = (float*)d_out;

    cudaFuncSetAttribute(k_hmma_gemm2,
                         cudaFuncAttributeMaxDynamicSharedMemorySize, HMMA_SMEM);
    cudaFuncSetAttribute(k_hmma_proj,
                         cudaFuncAttributeMaxDynamicSharedMemorySize, HMMA_SMEM);
    cudaFuncSetAttribute(k_hmma_vocab,
                         cudaFuncAttributeMaxDynamicSharedMemorySize, VOC_SMEM);

    gather_kernel<<<SPANS, 256>>>(H, pairs);
    posw_kernel<<<SPAN_L, DIM>>>(pos_emb, W1, b1);
    conv_B<<<(VOCAB * EMB + 255) / 256, 256>>>(Wdec);
    conv_W2<<<dim3(DIM / 32, DIM / 32), 256>>>(W2);
    conv_Wp<<<dim3(EMB / 32, DIM / 32), 256>>>(Wp);
    k_gemm_span<<<dim3(DIM / 128, SPANS / 64, KSPLIT), 256>>>(W1);
    reduce_U<<<(SPANS * DIM + 255) / 256, 256>>>();
    fuse_ln1<<<ROWS, 256>>>(g1, be1);
    k_hmma_gemm2<<<dim3(DIM / 128, ROWS / 128, 1), 256, HMMA_SMEM>>>();
    fuse_ln2<<<ROWS, 256>>>(b2, g2, be2);
    k_hmma_proj<<<dim3(1, ROWS / 128, 3), 256, HMMA_SMEM>>>();
    conv_A<<<(ROWS * EMB + 255) / 256, 256>>>(bp);
    k_hmma_vocab<<<dim3(VN_PAD / 256, ROWS / 128, 1), 512, VOC_SMEM>>>(out);
}